// round 12
// baseline (speedup 1.0000x reference)
#include <cuda_runtime.h>
#include <cuda_fp16.h>
#include <cuda_bf16.h>
#include <cstdint>

#define N_NODES   100000
#define N_EDGES   1600000
#define IN_FEATS  64
#define OUT_FEATS 64
#define DIM       3
#define N_KERNELS 4
#define KH        (N_KERNELS * OUT_FEATS)   // 256

#define SCAN_BLOCK 512
#define NBLK_SCAN  ((N_NODES + SCAN_BLOCK - 1) / SCAN_BLOCK)   // 196

// ---- scratch (allocation-free rule) ----
__device__ __half  g_h[(size_t)N_NODES * KH];   // node projections fp16 (51 MB)
__device__ __half  g_W16[KH * IN_FEATS];        // W_fc fp16 (32 KB, L1-resident)
__device__ int     g_count[N_NODES];            // out-degree (by src) histogram
__device__ int     g_offsets[N_NODES + 1];      // CSR offsets (by src)
__device__ int     g_cursor[N_NODES];           // fill cursors
__device__ int     g_bsum[NBLK_SCAN];           // scan block sums
__device__ float4  g_rec[N_EDGES];              // {dst_bits, px, py, pz} grouped by src
__device__ int     g_rsrc[N_EDGES];             // src of each record slot

// ---------------------------------------------------------------------------
// Kernel 0: fused W->fp16 conversion + zero histogram
// ---------------------------------------------------------------------------
__global__ void wconv_zero_kernel(const float* __restrict__ W_fc) {
    int i = blockIdx.x * blockDim.x + threadIdx.x;
    if (i < N_NODES) g_count[i] = 0;
    if (i < KH * IN_FEATS / 2) {
        float2 v = reinterpret_cast<const float2*>(W_fc)[i];
        reinterpret_cast<__half2*>(g_W16)[i] = __floats2half2_rn(v.x, v.y);
    }
}

// ---------------------------------------------------------------------------
// Histogram of src
// ---------------------------------------------------------------------------
__global__ void hist_kernel(const int* __restrict__ src) {
    int e = blockIdx.x * blockDim.x + threadIdx.x;
    if (e < N_EDGES) atomicAdd(&g_count[src[e]], 1);
}

// ---------------------------------------------------------------------------
// Two-level exclusive scan: g_count -> g_offsets (+ cursor copy)
// ---------------------------------------------------------------------------
__global__ __launch_bounds__(SCAN_BLOCK) void scan1_kernel() {
    __shared__ int tmp[SCAN_BLOCK];
    int t = threadIdx.x;
    int i = blockIdx.x * SCAN_BLOCK + t;
    int x = (i < N_NODES) ? g_count[i] : 0;
    tmp[t] = x;
    __syncthreads();
#pragma unroll
    for (int off = 1; off < SCAN_BLOCK; off <<= 1) {
        int v = (t >= off) ? tmp[t - off] : 0;
        __syncthreads();
        tmp[t] += v;
        __syncthreads();
    }
    if (i < N_NODES) g_offsets[i] = tmp[t] - x;
    if (t == SCAN_BLOCK - 1) g_bsum[blockIdx.x] = tmp[t];
}

__global__ __launch_bounds__(256) void scan2_kernel() {
    __shared__ int tmp[256];
    int t = threadIdx.x;
    int x = (t < NBLK_SCAN) ? g_bsum[t] : 0;
    tmp[t] = x;
    __syncthreads();
#pragma unroll
    for (int off = 1; off < 256; off <<= 1) {
        int v = (t >= off) ? tmp[t - off] : 0;
        __syncthreads();
        tmp[t] += v;
        __syncthreads();
    }
    if (t < NBLK_SCAN) g_bsum[t] = tmp[t] - x;
}

__global__ __launch_bounds__(SCAN_BLOCK) void scan3_kernel() {
    int i = blockIdx.x * SCAN_BLOCK + threadIdx.x;
    if (i < N_NODES) {
        int v = g_offsets[i] + g_bsum[blockIdx.x];
        g_offsets[i] = v;
        g_cursor[i]  = v;
    }
    if (i == 0) g_offsets[N_NODES] = N_EDGES;
}

// ---------------------------------------------------------------------------
// Binning: records {dst, pseudo} grouped by SRC (+ src sidecar array)
// ---------------------------------------------------------------------------
__global__ __launch_bounds__(256) void bin_kernel(const float* __restrict__ pseudo,
                                                  const int*   __restrict__ src,
                                                  const int*   __restrict__ dst) {
    int e = blockIdx.x * blockDim.x + threadIdx.x;
    if (e >= N_EDGES) return;
    float4 rec;
    rec.x = __int_as_float(__ldg(dst + e));
    rec.y = __ldg(pseudo + 3*e + 0);
    rec.z = __ldg(pseudo + 3*e + 1);
    rec.w = __ldg(pseudo + 3*e + 2);
    int s = __ldg(src + e);
    int pos = atomicAdd(&g_cursor[s], 1);
    g_rec[pos]  = rec;
    g_rsrc[pos] = s;
}

// ---------------------------------------------------------------------------
// Kernel 1: PTX-mma projection + fused out = feat + bias (unchanged, 35 us)
// ---------------------------------------------------------------------------
#define NT    128
#define AS_LD 72

__global__ __launch_bounds__(256) void proj_mma_kernel(const float* __restrict__ feat,
                                                       const float* __restrict__ bias,
                                                       float* __restrict__ out) {
    __shared__ __half As[NT * AS_LD];        // 18 KB

    const int tid  = threadIdx.x;
    const int warp = tid >> 5;
    const int lane = tid & 31;
    const int g    = lane >> 2;
    const int t    = lane & 3;
    const int node0 = blockIdx.x * NT;

    const float4* fsrc = reinterpret_cast<const float4*>(feat + (size_t)node0 * IN_FEATS);
    float4*       odst = reinterpret_cast<float4*>(out + (size_t)node0 * IN_FEATS);
    const float4* bp   = reinterpret_cast<const float4*>(bias);
    const int lim4 = (min(NT, N_NODES - node0)) * (IN_FEATS / 4);
#pragma unroll
    for (int q = 0; q < 8; q++) {
        int i = tid + q * 256;
        float4 v = (i < lim4) ? fsrc[i] : make_float4(0.f, 0.f, 0.f, 0.f);
        int n = i >> 4;
        int c = (i & 15) * 4;
        __half2* adst = reinterpret_cast<__half2*>(As + n * AS_LD + c);
        adst[0] = __floats2half2_rn(v.x, v.y);
        adst[1] = __floats2half2_rn(v.z, v.w);
        if (i < lim4) {
            float4 b = __ldg(bp + (i & 15));
            v.x += b.x; v.y += b.y; v.z += b.z; v.w += b.w;
            odst[i] = v;
        }
    }
    __syncthreads();

    const int n0w = warp * 32;
    uint32_t B[4][4][2];
#pragma unroll
    for (int nt = 0; nt < 4; nt++) {
        const int o = n0w + nt * 8 + g;
        const uint32_t* wrow = reinterpret_cast<const uint32_t*>(g_W16 + o * IN_FEATS);
#pragma unroll
        for (int k = 0; k < 4; k++) {
            B[nt][k][0] = __ldg(wrow + k * 8 + t);
            B[nt][k][1] = __ldg(wrow + k * 8 + t + 4);
        }
    }

    const uint32_t* As32 = reinterpret_cast<const uint32_t*>(As);

#pragma unroll
    for (int mi = 0; mi < 8; mi++) {
        const int r0 = mi * 16 + g;
        uint32_t A[4][4];
#pragma unroll
        for (int k = 0; k < 4; k++) {
            A[k][0] = As32[(size_t)r0       * (AS_LD/2) + k * 8 + t];
            A[k][1] = As32[(size_t)(r0 + 8) * (AS_LD/2) + k * 8 + t];
            A[k][2] = As32[(size_t)r0       * (AS_LD/2) + k * 8 + t + 4];
            A[k][3] = As32[(size_t)(r0 + 8) * (AS_LD/2) + k * 8 + t + 4];
        }

        const int nodeA = node0 + mi * 16 + g;
        const int nodeB = nodeA + 8;
#pragma unroll
        for (int nt = 0; nt < 4; nt++) {
            float c0 = 0.f, c1 = 0.f, c2 = 0.f, c3 = 0.f;
#pragma unroll
            for (int k = 0; k < 4; k++) {
                asm volatile(
                    "mma.sync.aligned.m16n8k16.row.col.f32.f16.f16.f32 "
                    "{%0,%1,%2,%3}, {%4,%5,%6,%7}, {%8,%9}, {%0,%1,%2,%3};"
                    : "+f"(c0), "+f"(c1), "+f"(c2), "+f"(c3)
                    : "r"(A[k][0]), "r"(A[k][1]), "r"(A[k][2]), "r"(A[k][3]),
                      "r"(B[nt][k][0]), "r"(B[nt][k][1]));
            }
            const int col = n0w + nt * 8 + 2 * t;
            if (nodeA < N_NODES)
                *reinterpret_cast<__half2*>(g_h + (size_t)nodeA * KH + col) =
                    __floats2half2_rn(c0, c1);
            if (nodeB < N_NODES)
                *reinterpret_cast<__half2*>(g_h + (size_t)nodeB * KH + col) =
                    __floats2half2_rn(c2, c3);
        }
    }
}

// ---------------------------------------------------------------------------
// Kernel 2: src-sorted edge scatter.
// 8 threads per edge, edges walked in src-sorted record order:
// consecutive edges share src -> the 4 edge-groups of a warp gather the SAME
// h row (broadcast wavefronts, L1 hits) instead of 4 random rows.
// ---------------------------------------------------------------------------
__global__ __launch_bounds__(256) void edge2_kernel(const float* __restrict__ mu,
                                                    const float* __restrict__ inv_sigma,
                                                    float* __restrict__ out) {
    const int gid = blockIdx.x * blockDim.x + threadIdx.x;
    const int i   = gid >> 3;                  // record index (src-sorted)
    if (i >= N_EDGES) return;

    const int lane = threadIdx.x & 31;
    const int sub  = gid & 7;                  // 0..7 within edge group
    const int kid  = sub & 3;                  // Gaussian kernel this lane evaluates

    // record: {dst, px, py, pz}; sequential 16B load (broadcast in group)
    float4 rec = __ldg(g_rec + i);
    const int d = __float_as_int(rec.x);
    const int s = __ldg(g_rsrc + i);

    float d0 = rec.y - __ldg(mu + kid*3 + 0);
    float d1 = rec.z - __ldg(mu + kid*3 + 1);
    float d2 = rec.w - __ldg(mu + kid*3 + 2);
    float s0 = __ldg(inv_sigma + kid*3 + 0);
    float s1 = __ldg(inv_sigma + kid*3 + 1);
    float s2 = __ldg(inv_sigma + kid*3 + 2);

    float acc = d0*d0*s0*s0 + d1*d1*s1*s1 + d2*d2*s2*s2;
    float gv  = __expf(-0.5f * acc);

    const unsigned FULL = 0xffffffffu;
    const int base = lane & 24;
    float g0 = __shfl_sync(FULL, gv, base + 0);
    float g1 = __shfl_sync(FULL, gv, base + 1);
    float g2 = __shfl_sync(FULL, gv, base + 2);
    float g3 = __shfl_sync(FULL, gv, base + 3);

    // Gather h[src] row (same src across the warp most of the time -> L1 hits)
    const float4* hp = reinterpret_cast<const float4*>(g_h + (size_t)s * KH);
    float4 r0 = __ldg(hp + 0*8 + sub);
    float4 r1 = __ldg(hp + 1*8 + sub);
    float4 r2 = __ldg(hp + 2*8 + sub);
    float4 r3 = __ldg(hp + 3*8 + sub);

    const __half2* h0 = reinterpret_cast<const __half2*>(&r0);
    const __half2* h1 = reinterpret_cast<const __half2*>(&r1);
    const __half2* h2 = reinterpret_cast<const __half2*>(&r2);
    const __half2* h3 = reinterpret_cast<const __half2*>(&r3);

    float m[8];
#pragma unroll
    for (int q = 0; q < 4; q++) {
        float2 a = __half22float2(h0[q]);
        float2 b = __half22float2(h1[q]);
        float2 c = __half22float2(h2[q]);
        float2 dd = __half22float2(h3[q]);
        m[2*q+0] = g0*a.x + g1*b.x + g2*c.x + g3*dd.x;
        m[2*q+1] = g0*a.y + g1*b.y + g2*c.y + g3*dd.y;
    }

    float* op = out + (size_t)d * OUT_FEATS + sub * 8;
    asm volatile("red.global.add.v4.f32 [%0], {%1, %2, %3, %4};"
                 :: "l"(op), "f"(m[0]), "f"(m[1]), "f"(m[2]), "f"(m[3])
                 : "memory");
    asm volatile("red.global.add.v4.f32 [%0], {%1, %2, %3, %4};"
                 :: "l"(op + 4), "f"(m[4]), "f"(m[5]), "f"(m[6]), "f"(m[7])
                 : "memory");
}

// ---------------------------------------------------------------------------
// Launch
// ---------------------------------------------------------------------------
extern "C" void kernel_launch(void* const* d_in, const int* in_sizes, int n_in,
                              void* d_out, int out_size) {
    const float* feat      = (const float*)d_in[0];   // [N, 64]
    const float* pseudo    = (const float*)d_in[1];   // [E, 3]
    const int*   src       = (const int*)  d_in[2];   // [E]
    const int*   dst       = (const int*)  d_in[3];   // [E]
    const float* W_fc      = (const float*)d_in[4];   // [256, 64]
    const float* mu        = (const float*)d_in[5];   // [4, 3]
    const float* inv_sigma = (const float*)d_in[6];   // [4, 3]
    const float* bias      = (const float*)d_in[7];   // [64]
    float* out = (float*)d_out;                       // [N, 64]

    // 0) W->fp16 + zero hist (fused)
    wconv_zero_kernel<<<(N_NODES + 255) / 256, 256>>>(W_fc);

    // src-CSR build
    hist_kernel<<<(N_EDGES + 255) / 256, 256>>>(src);
    scan1_kernel<<<NBLK_SCAN, SCAN_BLOCK>>>();
    scan2_kernel<<<1, 256>>>();
    scan3_kernel<<<NBLK_SCAN, SCAN_BLOCK>>>();
    bin_kernel<<<(N_EDGES + 255) / 256, 256>>>(pseudo, src, dst);

    // 1) tensor-core projection + out = feat + bias
    proj_mma_kernel<<<(N_NODES + NT - 1) / NT, 256>>>(feat, bias, out);

    // 2) src-sorted edge scatter with vector atomics
    {
        long long threads = (long long)N_EDGES * 8;
        int blocks = (int)((threads + 255) / 256);            // 50000
        edge2_kernel<<<blocks, 256>>>(mu, inv_sigma, out);
    }
}

// round 14
// speedup vs baseline: 1.1080x; 1.1080x over previous
#include <cuda_runtime.h>
#include <cuda_fp16.h>
#include <cuda_bf16.h>
#include <cstdint>

#define N_NODES   100000
#define N_EDGES   1600000
#define IN_FEATS  64
#define OUT_FEATS 64
#define DIM       3
#define N_KERNELS 4
#define KH        (N_KERNELS * OUT_FEATS)   // 256

#define SCAN_BLOCK 512
#define NBLK_SCAN  ((N_NODES + SCAN_BLOCK - 1) / SCAN_BLOCK)   // 196

// ---- scratch (allocation-free rule) ----
__device__ __half  g_h[(size_t)N_NODES * KH];   // node projections fp16 (51 MB)
__device__ __half  g_W16[KH * IN_FEATS];        // W_fc fp16 (32 KB, L1-resident)
__device__ int     g_count[N_NODES];            // in-degree (by dst) histogram
__device__ int     g_offsets[N_NODES + 1];      // CSR offsets (by dst)
__device__ int     g_cursor[N_NODES];           // fill cursors
__device__ int     g_bsum[NBLK_SCAN];           // scan block sums
__device__ float4  g_rec[N_EDGES];              // {src_bits, px, py, pz} grouped by dst

// ---------------------------------------------------------------------------
// Kernel 0: fused W->fp16 conversion + zero histogram
// ---------------------------------------------------------------------------
__global__ void wconv_zero_kernel(const float* __restrict__ W_fc) {
    int i = blockIdx.x * blockDim.x + threadIdx.x;
    if (i < N_NODES) g_count[i] = 0;
    if (i < KH * IN_FEATS / 2) {
        float2 v = reinterpret_cast<const float2*>(W_fc)[i];
        reinterpret_cast<__half2*>(g_W16)[i] = __floats2half2_rn(v.x, v.y);
    }
}

// ---------------------------------------------------------------------------
// Histogram of dst
// ---------------------------------------------------------------------------
__global__ void hist_kernel(const int* __restrict__ dst) {
    int e = blockIdx.x * blockDim.x + threadIdx.x;
    if (e < N_EDGES) atomicAdd(&g_count[dst[e]], 1);
}

// ---------------------------------------------------------------------------
// Two-level exclusive scan: g_count -> g_offsets (+ cursor copy)
// ---------------------------------------------------------------------------
__global__ __launch_bounds__(SCAN_BLOCK) void scan1_kernel() {
    __shared__ int tmp[SCAN_BLOCK];
    int t = threadIdx.x;
    int i = blockIdx.x * SCAN_BLOCK + t;
    int x = (i < N_NODES) ? g_count[i] : 0;
    tmp[t] = x;
    __syncthreads();
#pragma unroll
    for (int off = 1; off < SCAN_BLOCK; off <<= 1) {
        int v = (t >= off) ? tmp[t - off] : 0;
        __syncthreads();
        tmp[t] += v;
        __syncthreads();
    }
    if (i < N_NODES) g_offsets[i] = tmp[t] - x;
    if (t == SCAN_BLOCK - 1) g_bsum[blockIdx.x] = tmp[t];
}

__global__ __launch_bounds__(256) void scan2_kernel() {
    __shared__ int tmp[256];
    int t = threadIdx.x;
    int x = (t < NBLK_SCAN) ? g_bsum[t] : 0;
    tmp[t] = x;
    __syncthreads();
#pragma unroll
    for (int off = 1; off < 256; off <<= 1) {
        int v = (t >= off) ? tmp[t - off] : 0;
        __syncthreads();
        tmp[t] += v;
        __syncthreads();
    }
    if (t < NBLK_SCAN) g_bsum[t] = tmp[t] - x;
}

__global__ __launch_bounds__(SCAN_BLOCK) void scan3_kernel() {
    int i = blockIdx.x * SCAN_BLOCK + threadIdx.x;
    if (i < N_NODES) {
        int v = g_offsets[i] + g_bsum[blockIdx.x];
        g_offsets[i] = v;
        g_cursor[i]  = v;
    }
    if (i == 0) g_offsets[N_NODES] = N_EDGES;
}

// ---------------------------------------------------------------------------
// Binning: records {src, pseudo} grouped by DST (streaming store hint)
// ---------------------------------------------------------------------------
__global__ __launch_bounds__(256) void bin_kernel(const float* __restrict__ pseudo,
                                                  const int*   __restrict__ src,
                                                  const int*   __restrict__ dst) {
    int e = blockIdx.x * blockDim.x + threadIdx.x;
    if (e >= N_EDGES) return;
    float4 rec;
    rec.x = __int_as_float(__ldg(src + e));
    rec.y = __ldg(pseudo + 3*e + 0);
    rec.z = __ldg(pseudo + 3*e + 1);
    rec.w = __ldg(pseudo + 3*e + 2);
    int d = __ldg(dst + e);
    int pos = atomicAdd(&g_cursor[d], 1);
    asm volatile("st.global.cs.v4.f32 [%0], {%1, %2, %3, %4};"
                 :: "l"(g_rec + pos), "f"(rec.x), "f"(rec.y), "f"(rec.z), "f"(rec.w)
                 : "memory");
}

// ---------------------------------------------------------------------------
// Kernel 1: PTX-mma projection (35 us). out written by agg_kernel only.
// ---------------------------------------------------------------------------
#define NT    128
#define AS_LD 72

__global__ __launch_bounds__(256) void proj_mma_kernel(const float* __restrict__ feat) {
    __shared__ __half As[NT * AS_LD];        // 18 KB

    const int tid  = threadIdx.x;
    const int warp = tid >> 5;
    const int lane = tid & 31;
    const int g    = lane >> 2;
    const int t    = lane & 3;
    const int node0 = blockIdx.x * NT;

    const float4* fsrc = reinterpret_cast<const float4*>(feat + (size_t)node0 * IN_FEATS);
    const int lim4 = (min(NT, N_NODES - node0)) * (IN_FEATS / 4);
#pragma unroll
    for (int q = 0; q < 8; q++) {
        int i = tid + q * 256;
        float4 v = (i < lim4) ? fsrc[i] : make_float4(0.f, 0.f, 0.f, 0.f);
        int n = i >> 4;
        int c = (i & 15) * 4;
        __half2* adst = reinterpret_cast<__half2*>(As + n * AS_LD + c);
        adst[0] = __floats2half2_rn(v.x, v.y);
        adst[1] = __floats2half2_rn(v.z, v.w);
    }
    __syncthreads();

    const int n0w = warp * 32;
    uint32_t B[4][4][2];
#pragma unroll
    for (int nt = 0; nt < 4; nt++) {
        const int o = n0w + nt * 8 + g;
        const uint32_t* wrow = reinterpret_cast<const uint32_t*>(g_W16 + o * IN_FEATS);
#pragma unroll
        for (int k = 0; k < 4; k++) {
            B[nt][k][0] = __ldg(wrow + k * 8 + t);
            B[nt][k][1] = __ldg(wrow + k * 8 + t + 4);
        }
    }

    const uint32_t* As32 = reinterpret_cast<const uint32_t*>(As);

#pragma unroll
    for (int mi = 0; mi < 8; mi++) {
        const int r0 = mi * 16 + g;
        uint32_t A[4][4];
#pragma unroll
        for (int k = 0; k < 4; k++) {
            A[k][0] = As32[(size_t)r0       * (AS_LD/2) + k * 8 + t];
            A[k][1] = As32[(size_t)(r0 + 8) * (AS_LD/2) + k * 8 + t];
            A[k][2] = As32[(size_t)r0       * (AS_LD/2) + k * 8 + t + 4];
            A[k][3] = As32[(size_t)(r0 + 8) * (AS_LD/2) + k * 8 + t + 4];
        }

        const int nodeA = node0 + mi * 16 + g;
        const int nodeB = nodeA + 8;
#pragma unroll
        for (int nt = 0; nt < 4; nt++) {
            float c0 = 0.f, c1 = 0.f, c2 = 0.f, c3 = 0.f;
#pragma unroll
            for (int k = 0; k < 4; k++) {
                asm volatile(
                    "mma.sync.aligned.m16n8k16.row.col.f32.f16.f16.f32 "
                    "{%0,%1,%2,%3}, {%4,%5,%6,%7}, {%8,%9}, {%0,%1,%2,%3};"
                    : "+f"(c0), "+f"(c1), "+f"(c2), "+f"(c3)
                    : "r"(A[k][0]), "r"(A[k][1]), "r"(A[k][2]), "r"(A[k][3]),
                      "r"(B[nt][k][0]), "r"(B[nt][k][1]));
            }
            const int col = n0w + nt * 8 + 2 * t;
            if (nodeA < N_NODES)
                *reinterpret_cast<__half2*>(g_h + (size_t)nodeA * KH + col) =
                    __floats2half2_rn(c0, c1);
            if (nodeB < N_NODES)
                *reinterpret_cast<__half2*>(g_h + (size_t)nodeB * KH + col) =
                    __floats2half2_rn(c2, c3);
        }
    }
}

// ---------------------------------------------------------------------------
// Kernel 2: atomic-free aggregation, software-pipelined.
// One warp per dst node; 4 edges per iteration (group = lane>>3, sub = lane&7,
// kid = lane&3). Records + h rows prefetched one iteration ahead.
// out[v] = feat[v] + bias + acc   (plain stores, no atomics)
// ---------------------------------------------------------------------------
#define AGG_WARPS 8

__global__ __launch_bounds__(AGG_WARPS * 32) void agg_kernel(const float* __restrict__ feat,
                                                             const float* __restrict__ bias,
                                                             const float* __restrict__ mu,
                                                             const float* __restrict__ inv_sigma,
                                                             float* __restrict__ out) {
    const int warp = threadIdx.x >> 5;
    const int lane = threadIdx.x & 31;
    const int v = blockIdx.x * AGG_WARPS + warp;
    if (v >= N_NODES) return;

    const int beg = g_offsets[v];
    const int end = g_offsets[v + 1];

    const int group = lane >> 3;
    const int sub   = lane & 7;
    const int kid   = lane & 3;
    const int gbase = lane & 24;

    // per-lane Gaussian params (kernel kid)
    const float m0 = __ldg(mu + kid*3 + 0);
    const float m1 = __ldg(mu + kid*3 + 1);
    const float m2 = __ldg(mu + kid*3 + 2);
    float s0 = __ldg(inv_sigma + kid*3 + 0);
    float s1 = __ldg(inv_sigma + kid*3 + 1);
    float s2 = __ldg(inv_sigma + kid*3 + 2);
    const float q0 = -0.5f * s0 * s0;
    const float q1 = -0.5f * s1 * s1;
    const float q2 = -0.5f * s2 * s2;

    const unsigned FULL = 0xffffffffu;
    const float4 Z4 = make_float4(0.f, 0.f, 0.f, 0.f);

    float acc[8];
#pragma unroll
    for (int j = 0; j < 8; j++) acc[j] = 0.f;

    // ---- pipeline prologue: rec + h rows for iteration 0 ----
    bool   aC = (beg + group) < end;
    float4 rC = aC ? __ldg(g_rec + beg + group) : Z4;
    float4 h0C = Z4, h1C = Z4, h2C = Z4, h3C = Z4;
    if (aC) {
        const float4* hp = reinterpret_cast<const float4*>(
            g_h + (size_t)__float_as_int(rC.x) * KH);
        h0C = __ldg(hp + 0*8 + sub);
        h1C = __ldg(hp + 1*8 + sub);
        h2C = __ldg(hp + 2*8 + sub);
        h3C = __ldg(hp + 3*8 + sub);
    }

    for (int i = beg; i < end; i += 4) {
        // prefetch next record (chain head for iteration i+4)
        const bool aN = (i + 4 + group) < end;
        float4 rN = aN ? __ldg(g_rec + i + 4 + group) : Z4;

        // gaussian weight for the current edge
        float d0 = rC.y - m0, d1 = rC.z - m1, d2 = rC.w - m2;
        float gv = aC ? __expf(q0*d0*d0 + q1*d1*d1 + q2*d2*d2) : 0.f;
        float g0 = __shfl_sync(FULL, gv, gbase + 0);
        float g1 = __shfl_sync(FULL, gv, gbase + 1);
        float g2 = __shfl_sync(FULL, gv, gbase + 2);
        float g3 = __shfl_sync(FULL, gv, gbase + 3);

        // issue h loads for the NEXT iteration before consuming current
        float4 h0N = Z4, h1N = Z4, h2N = Z4, h3N = Z4;
        if (aN) {
            const float4* hp = reinterpret_cast<const float4*>(
                g_h + (size_t)__float_as_int(rN.x) * KH);
            h0N = __ldg(hp + 0*8 + sub);
            h1N = __ldg(hp + 1*8 + sub);
            h2N = __ldg(hp + 2*8 + sub);
            h3N = __ldg(hp + 3*8 + sub);
        }

        // consume current h rows
        const __half2* p0 = reinterpret_cast<const __half2*>(&h0C);
        const __half2* p1 = reinterpret_cast<const __half2*>(&h1C);
        const __half2* p2 = reinterpret_cast<const __half2*>(&h2C);
        const __half2* p3 = reinterpret_cast<const __half2*>(&h3C);
#pragma unroll
        for (int q = 0; q < 4; q++) {
            float2 a = __half22float2(p0[q]);
            float2 b = __half22float2(p1[q]);
            float2 c = __half22float2(p2[q]);
            float2 d = __half22float2(p3[q]);
            acc[2*q+0] += g0*a.x + g1*b.x + g2*c.x + g3*d.x;
            acc[2*q+1] += g0*a.y + g1*b.y + g2*c.y + g3*d.y;
        }

        // rotate pipeline
        aC = aN; rC = rN;
        h0C = h0N; h1C = h1N; h2C = h2N; h3C = h3N;
    }

    // reduce across the 4 groups (lanes l, l+8, l+16, l+24 share channel set)
#pragma unroll
    for (int j = 0; j < 8; j++) {
        acc[j] += __shfl_down_sync(FULL, acc[j], 16);
        acc[j] += __shfl_down_sync(FULL, acc[j], 8);
    }

    // lanes 0..7 write channels sub*8..sub*8+7 with residual + bias
    if (lane < 8) {
        const float4* fp = reinterpret_cast<const float4*>(feat + (size_t)v * OUT_FEATS + lane * 8);
        const float4* bp = reinterpret_cast<const float4*>(bias + lane * 8);
        float4 fa = __ldg(fp + 0), fb = __ldg(fp + 1);
        float4 ba = __ldg(bp + 0), bb = __ldg(bp + 1);
        float4 oa, ob;
        oa.x = fa.x + ba.x + acc[0];
        oa.y = fa.y + ba.y + acc[1];
        oa.z = fa.z + ba.z + acc[2];
        oa.w = fa.w + ba.w + acc[3];
        ob.x = fb.x + bb.x + acc[4];
        ob.y = fb.y + bb.y + acc[5];
        ob.z = fb.z + bb.z + acc[6];
        ob.w = fb.w + bb.w + acc[7];
        float4* op = reinterpret_cast<float4*>(out + (size_t)v * OUT_FEATS + lane * 8);
        op[0] = oa;
        op[1] = ob;
    }
}

// ---------------------------------------------------------------------------
// Launch
// ---------------------------------------------------------------------------
extern "C" void kernel_launch(void* const* d_in, const int* in_sizes, int n_in,
                              void* d_out, int out_size) {
    const float* feat      = (const float*)d_in[0];   // [N, 64]
    const float* pseudo    = (const float*)d_in[1];   // [E, 3]
    const int*   src       = (const int*)  d_in[2];   // [E]
    const int*   dst       = (const int*)  d_in[3];   // [E]
    const float* W_fc      = (const float*)d_in[4];   // [256, 64]
    const float* mu        = (const float*)d_in[5];   // [4, 3]
    const float* inv_sigma = (const float*)d_in[6];   // [4, 3]
    const float* bias      = (const float*)d_in[7];   // [64]
    float* out = (float*)d_out;                       // [N, 64]

    // 0) W->fp16 + zero hist (fused)
    wconv_zero_kernel<<<(N_NODES + 255) / 256, 256>>>(W_fc);

    // dst-CSR build
    hist_kernel<<<(N_EDGES + 255) / 256, 256>>>(dst);
    scan1_kernel<<<NBLK_SCAN, SCAN_BLOCK>>>();
    scan2_kernel<<<1, 256>>>();
    scan3_kernel<<<NBLK_SCAN, SCAN_BLOCK>>>();
    bin_kernel<<<(N_EDGES + 255) / 256, 256>>>(pseudo, src, dst);

    // 1) tensor-core projection
    proj_mma_kernel<<<(N_NODES + NT - 1) / NT, 256>>>(feat);

    // 2) atomic-free pipelined aggregation + residual + bias
    agg_kernel<<<(N_NODES + AGG_WARPS - 1) / AGG_WARPS, AGG_WARPS * 32>>>(
        feat, bias, mu, inv_sigma, out);
}